// round 3
// baseline (speedup 1.0000x reference)
#include <cuda_runtime.h>
#include <cfloat>

// Problem constants
#define NV   32768            // B*S vectors
#define DIM  512              // feature dim
#define KC   4096             // codes per layer
#define LL   3                // layers

// GEMM tiling
#define BM 128
#define BN 128
#define BK 16
#define TM 8
#define TN 8

#define UPD_ROWS   4
#define UPD_BLOCKS (NV / UPD_ROWS)   // 8192

// Output layout (float32, positional flatten)
#define OUT_QSUM 0
#define OUT_IDX  16777216
#define OUT_COMMIT 16875520
#define OUT_PERP   16875521

// Scratch (device globals: no allocation allowed)
__device__ float g_res[NV * DIM];            // residual, 64 MB
__device__ int   g_idx[NV];                  // per-layer argmin result
__device__ int   g_counts[LL * KC];          // histogram for perplexity
__device__ float g_enorm[LL * KC];           // ||e||^2
__device__ float g_commit[LL * UPD_BLOCKS];  // per-block commit partial sums

// ---------------------------------------------------------------------------
// zero the histogram (residual copy is done via cudaMemcpyAsync on host side)
// ---------------------------------------------------------------------------
__global__ void zero_counts_kernel() {
    int i = blockIdx.x * blockDim.x + threadIdx.x;
    if (i < LL * KC) g_counts[i] = 0;
}

// ---------------------------------------------------------------------------
// ||e||^2 for every codebook row (all layers): one warp per row
// ---------------------------------------------------------------------------
__global__ void enorm_kernel(const float* __restrict__ cb) {
    int gw = (blockIdx.x * blockDim.x + threadIdx.x) >> 5;
    int lane = threadIdx.x & 31;
    if (gw >= LL * KC) return;
    const float4* row = reinterpret_cast<const float4*>(cb) + (size_t)gw * (DIM / 4);
    float s = 0.f;
    #pragma unroll
    for (int c = lane; c < DIM / 4; c += 32) {
        float4 v = row[c];
        s += v.x * v.x + v.y * v.y + v.z * v.z + v.w * v.w;
    }
    #pragma unroll
    for (int o = 16; o > 0; o >>= 1) s += __shfl_xor_sync(0xffffffffu, s, o);
    if (lane == 0) g_enorm[gw] = s;
}

// ---------------------------------------------------------------------------
// Fused GEMM + row-argmin, double-buffered SMEM:
//   score(n) = ||E_n||^2 - 2 * <r, E_n>   (||r||^2 constant per row -> dropped)
// Each CTA owns BM rows and loops over all K columns; running per-row argmin.
// ---------------------------------------------------------------------------
__global__ __launch_bounds__(256, 2)
void argmin_kernel(const float* __restrict__ E, int l) {
    __shared__ __align__(16) float As[2][BK][BM];
    __shared__ __align__(16) float Bs[2][BK][BN];
    __shared__ float sval[BM][16];
    __shared__ int   sidx[BM][16];

    const int tid = threadIdx.x;
    const int block_row = blockIdx.x * BM;
    const int tr = (tid >> 4) * TM;     // row offset of this thread's 8 rows
    const int tc = (tid & 15) * TN;     // col offset of this thread's 8 cols
    const float* __restrict__ enorm = &g_enorm[l * KC];

    // Per-thread load coordinates (two float4 slabs per tile)
    const int ldrow0 = tid >> 2;              // 0..63
    const int ldrow1 = (tid + 256) >> 2;      // 64..127
    const int ldkk = (tid & 3) << 2;          // 0,4,8,12

    float bestv[TM];
    int   besti[TM];
    #pragma unroll
    for (int i = 0; i < TM; i++) { bestv[i] = FLT_MAX; besti[i] = 0; }

    for (int n0 = 0; n0 < KC; n0 += BN) {
        float acc[TM][TN];
        #pragma unroll
        for (int i = 0; i < TM; i++)
            #pragma unroll
            for (int j = 0; j < TN; j++) acc[i][j] = 0.f;

        // Prologue: load k-slab 0 into buffer 0
        {
            float4 a0 = *reinterpret_cast<const float4*>(
                &g_res[(size_t)(block_row + ldrow0) * DIM + ldkk]);
            float4 a1 = *reinterpret_cast<const float4*>(
                &g_res[(size_t)(block_row + ldrow1) * DIM + ldkk]);
            float4 b0 = *reinterpret_cast<const float4*>(
                &E[(size_t)(n0 + ldrow0) * DIM + ldkk]);
            float4 b1 = *reinterpret_cast<const float4*>(
                &E[(size_t)(n0 + ldrow1) * DIM + ldkk]);
            As[0][ldkk + 0][ldrow0] = a0.x; As[0][ldkk + 1][ldrow0] = a0.y;
            As[0][ldkk + 2][ldrow0] = a0.z; As[0][ldkk + 3][ldrow0] = a0.w;
            As[0][ldkk + 0][ldrow1] = a1.x; As[0][ldkk + 1][ldrow1] = a1.y;
            As[0][ldkk + 2][ldrow1] = a1.z; As[0][ldkk + 3][ldrow1] = a1.w;
            Bs[0][ldkk + 0][ldrow0] = b0.x; Bs[0][ldkk + 1][ldrow0] = b0.y;
            Bs[0][ldkk + 2][ldrow0] = b0.z; Bs[0][ldkk + 3][ldrow0] = b0.w;
            Bs[0][ldkk + 0][ldrow1] = b1.x; Bs[0][ldkk + 1][ldrow1] = b1.y;
            Bs[0][ldkk + 2][ldrow1] = b1.z; Bs[0][ldkk + 3][ldrow1] = b1.w;
        }
        __syncthreads();

        for (int ks = 0; ks < DIM / BK; ks++) {
            const int cur = ks & 1;
            const int nxt = cur ^ 1;
            // Prefetch next slab into registers, then store to the other buffer
            float4 a0, a1, b0, b1;
            const bool have_next = (ks + 1 < DIM / BK);
            if (have_next) {
                int k0 = (ks + 1) * BK;
                a0 = *reinterpret_cast<const float4*>(
                    &g_res[(size_t)(block_row + ldrow0) * DIM + k0 + ldkk]);
                a1 = *reinterpret_cast<const float4*>(
                    &g_res[(size_t)(block_row + ldrow1) * DIM + k0 + ldkk]);
                b0 = *reinterpret_cast<const float4*>(
                    &E[(size_t)(n0 + ldrow0) * DIM + k0 + ldkk]);
                b1 = *reinterpret_cast<const float4*>(
                    &E[(size_t)(n0 + ldrow1) * DIM + k0 + ldkk]);
            }
            // Compute on current buffer
            #pragma unroll
            for (int k = 0; k < BK; k++) {
                float a[TM], b[TN];
                *reinterpret_cast<float4*>(&a[0]) =
                    *reinterpret_cast<const float4*>(&As[cur][k][tr]);
                *reinterpret_cast<float4*>(&a[4]) =
                    *reinterpret_cast<const float4*>(&As[cur][k][tr + 4]);
                *reinterpret_cast<float4*>(&b[0]) =
                    *reinterpret_cast<const float4*>(&Bs[cur][k][tc]);
                *reinterpret_cast<float4*>(&b[4]) =
                    *reinterpret_cast<const float4*>(&Bs[cur][k][tc + 4]);
                #pragma unroll
                for (int i = 0; i < TM; i++)
                    #pragma unroll
                    for (int j = 0; j < TN; j++)
                        acc[i][j] = fmaf(a[i], b[j], acc[i][j]);
            }
            if (have_next) {
                __syncthreads();   // everyone done reading buffer nxt (prev iter)
                As[nxt][ldkk + 0][ldrow0] = a0.x; As[nxt][ldkk + 1][ldrow0] = a0.y;
                As[nxt][ldkk + 2][ldrow0] = a0.z; As[nxt][ldkk + 3][ldrow0] = a0.w;
                As[nxt][ldkk + 0][ldrow1] = a1.x; As[nxt][ldkk + 1][ldrow1] = a1.y;
                As[nxt][ldkk + 2][ldrow1] = a1.z; As[nxt][ldkk + 3][ldrow1] = a1.w;
                Bs[nxt][ldkk + 0][ldrow0] = b0.x; Bs[nxt][ldkk + 1][ldrow0] = b0.y;
                Bs[nxt][ldkk + 2][ldrow0] = b0.z; Bs[nxt][ldkk + 3][ldrow0] = b0.w;
                Bs[nxt][ldkk + 0][ldrow1] = b1.x; Bs[nxt][ldkk + 1][ldrow1] = b1.y;
                Bs[nxt][ldkk + 2][ldrow1] = b1.z; Bs[nxt][ldkk + 3][ldrow1] = b1.w;
                __syncthreads();
            }
        }
        // Epilogue: fold into running argmin (cols traversed in increasing order
        // within each thread -> strict < keeps the FIRST minimum, like jnp.argmin)
        #pragma unroll
        for (int j = 0; j < TN; j++) {
            int col = n0 + tc + j;
            float en = __ldg(&enorm[col]);
            #pragma unroll
            for (int i = 0; i < TM; i++) {
                float v = fmaf(-2.f, acc[i][j], en);
                if (v < bestv[i]) { bestv[i] = v; besti[i] = col; }
            }
        }
        __syncthreads();   // before reusing buffers for next n0 tile
    }

    // Cross-thread reduction: 16 threads share each row; tie-break lowest index
    #pragma unroll
    for (int i = 0; i < TM; i++) {
        sval[tr + i][tid & 15] = bestv[i];
        sidx[tr + i][tid & 15] = besti[i];
    }
    __syncthreads();
    if (tid < BM) {
        float bv = sval[tid][0]; int bi = sidx[tid][0];
        #pragma unroll
        for (int c = 1; c < 16; c++) {
            float v = sval[tid][c]; int ii = sidx[tid][c];
            if (v < bv || (v == bv && ii < bi)) { bv = v; bi = ii; }
        }
        g_idx[block_row + tid] = bi;
    }
}

// ---------------------------------------------------------------------------
// Gather + STE + residual update + commit partials + histogram + index output
// 512 threads per block, 4 rows per block, float4 per thread
// ---------------------------------------------------------------------------
__global__ void update_kernel(const float* __restrict__ E,
                              float* __restrict__ qsum,
                              float* __restrict__ idx_out, int l) {
    __shared__ float red[512];
    int t = threadIdx.x;
    int row = blockIdx.x * UPD_ROWS + (t >> 7);
    int lane = t & 127;
    int idx = g_idx[row];

    const float4 q = reinterpret_cast<const float4*>(E)[(size_t)idx * (DIM / 4) + lane];
    float4* rp = reinterpret_cast<float4*>(g_res) + (size_t)row * (DIM / 4) + lane;
    float4 r = *rp;

    // Straight-through estimator, rounding-matched to reference: zf + (q - zf)
    float4 qst = make_float4(r.x + (q.x - r.x), r.y + (q.y - r.y),
                             r.z + (q.z - r.z), r.w + (q.w - r.w));
    float4* qp = reinterpret_cast<float4*>(qsum) + (size_t)row * (DIM / 4) + lane;
    if (l == 0) {
        *qp = qst;
    } else {
        float4 p = *qp;
        p.x += qst.x; p.y += qst.y; p.z += qst.z; p.w += qst.w;
        *qp = p;
    }

    float4 d = make_float4(r.x - q.x, r.y - q.y, r.z - q.z, r.w - q.w);
    *rp = d;   // residual for next layer
    float s = d.x * d.x + d.y * d.y + d.z * d.z + d.w * d.w;

    red[t] = s; __syncthreads();
    #pragma unroll
    for (int o = 256; o > 0; o >>= 1) { if (t < o) red[t] += red[t + o]; __syncthreads(); }
    if (t == 0) g_commit[l * UPD_BLOCKS + blockIdx.x] = red[0];

    if (lane == 0) {
        atomicAdd(&g_counts[l * KC + idx], 1);
        idx_out[row * LL] = (float)idx;   // indices stored as f32 in output
    }
}

// ---------------------------------------------------------------------------
// Scalars: commit loss + average perplexity (deterministic reductions)
// ---------------------------------------------------------------------------
__global__ void final_kernel(float* __restrict__ out) {
    __shared__ float red[256];
    __shared__ float perp_acc;
    int t = threadIdx.x;

    float s = 0.f;
    for (int i = t; i < LL * UPD_BLOCKS; i += 256) s += g_commit[i];
    red[t] = s; __syncthreads();
    #pragma unroll
    for (int o = 128; o > 0; o >>= 1) { if (t < o) red[t] += red[t + o]; __syncthreads(); }
    float commit = 0.25f * red[0] / (float)((long long)NV * DIM);
    __syncthreads();

    if (t == 0) perp_acc = 0.f;
    for (int l = 0; l < LL; l++) {
        __syncthreads();
        float p = 0.f;
        for (int i = t; i < KC; i += 256) {
            float ap = (float)g_counts[l * KC + i] / (float)NV;
            p += ap * logf(ap + 1e-10f);
        }
        red[t] = p; __syncthreads();
        #pragma unroll
        for (int o = 128; o > 0; o >>= 1) { if (t < o) red[t] += red[t + o]; __syncthreads(); }
        if (t == 0) perp_acc += expf(-red[0]);
    }
    __syncthreads();
    if (t == 0) {
        out[OUT_COMMIT] = commit;
        out[OUT_PERP]   = perp_acc / (float)LL;
    }
}

// ---------------------------------------------------------------------------
extern "C" void kernel_launch(void* const* d_in, const int* in_sizes, int n_in,
                              void* d_out, int out_size) {
    const float* z  = (const float*)d_in[0];   // [8, 4096, 512]
    const float* cb = (const float*)d_in[1];   // [3, 4096, 512]
    float* out = (float*)d_out;

    // residual <- z  (async D2D copy into the device-global scratch; capture-legal)
    float* res_ptr = nullptr;
    cudaGetSymbolAddress((void**)&res_ptr, g_res);
    cudaMemcpyAsync(res_ptr, z, (size_t)NV * DIM * sizeof(float),
                    cudaMemcpyDeviceToDevice);

    zero_counts_kernel<<<(LL * KC + 255) / 256, 256>>>();
    enorm_kernel<<<(LL * KC * 32) / 256, 256>>>(cb);

    for (int l = 0; l < LL; l++) {
        const float* E = cb + (size_t)l * KC * DIM;
        argmin_kernel<<<NV / BM, 256>>>(E, l);
        update_kernel<<<UPD_BLOCKS, 512>>>(E, out + OUT_QSUM, out + OUT_IDX + l, l);
    }
    final_kernel<<<1, 256>>>(out);
}

// round 7
// speedup vs baseline: 4.6026x; 4.6026x over previous
#include <cuda_runtime.h>
#include <cuda_bf16.h>
#include <cstdint>
#include <cfloat>

// ---------------------------------------------------------------------------
// Problem constants
// ---------------------------------------------------------------------------
#define NV   32768
#define DIM  512
#define KC   4096
#define LL   3

#define N_TILE 128
#define KB     32                  // bf16 K elems per chunk
#define NKC    (DIM / KB)          // 16
#define NT     (KC / N_TILE)       // 32
#define SROW   40                  // smem row stride in bf16 (80 B)

#define MARGIN 2.5f
#define CAP    4194304u

#define UPD_ROWS   4
#define UPD_BLOCKS (NV / UPD_ROWS)

// Output layout (float32, positional flatten)
#define OUT_QSUM   0
#define OUT_IDX    16777216
#define OUT_COMMIT 16875520
#define OUT_PERP   16875521

// ---------------------------------------------------------------------------
// Scratch (device globals)
// ---------------------------------------------------------------------------
__device__ float              g_res[NV * DIM];        // fp32 residual (exact)
__device__ __nv_bfloat16      g_r16[NV * DIM];        // bf16 residual mirror
__device__ __nv_bfloat16      g_cb16[LL * KC * DIM];  // bf16 codebooks
__device__ float              g_enorm[LL * KC];
__device__ int                g_counts[LL * KC];
__device__ float              g_commit[LL * UPD_BLOCKS];
__device__ unsigned long long g_best[NV];
__device__ unsigned int       g_cand[CAP];
__device__ unsigned int       g_ncand;

// ---------------------------------------------------------------------------
// Helpers
// ---------------------------------------------------------------------------
__device__ __forceinline__ uint32_t smem_u32(const void* p) {
    uint32_t a;
    asm("{ .reg .u64 t; cvta.to.shared.u64 t, %1; cvt.u32.u64 %0, t; }" : "=r"(a) : "l"(p));
    return a;
}
__device__ __forceinline__ void ldsm_x4(uint32_t& r0, uint32_t& r1,
                                        uint32_t& r2, uint32_t& r3, uint32_t addr) {
    asm volatile("ldmatrix.sync.aligned.m8n8.x4.shared.b16 {%0,%1,%2,%3}, [%4];"
                 : "=r"(r0), "=r"(r1), "=r"(r2), "=r"(r3) : "r"(addr));
}
__device__ __forceinline__ void ldsm_x2(uint32_t& r0, uint32_t& r1, uint32_t addr) {
    asm volatile("ldmatrix.sync.aligned.m8n8.x2.shared.b16 {%0,%1}, [%2];"
                 : "=r"(r0), "=r"(r1) : "r"(addr));
}
__device__ __forceinline__ void mma_bf16(float* c, uint32_t a0, uint32_t a1,
                                         uint32_t a2, uint32_t a3,
                                         uint32_t b0, uint32_t b1) {
    asm volatile("mma.sync.aligned.m16n8k16.row.col.f32.bf16.bf16.f32 "
                 "{%0,%1,%2,%3}, {%4,%5,%6,%7}, {%8,%9}, {%0,%1,%2,%3};"
                 : "+f"(c[0]), "+f"(c[1]), "+f"(c[2]), "+f"(c[3])
                 : "r"(a0), "r"(a1), "r"(a2), "r"(a3), "r"(b0), "r"(b1));
}
__device__ __forceinline__ uint32_t pack_bf2(float lo, float hi) {
    uint32_t l = __bfloat16_as_ushort(__float2bfloat16(lo));
    uint32_t h = __bfloat16_as_ushort(__float2bfloat16(hi));
    return (h << 16) | l;
}
__device__ __forceinline__ unsigned enc_f(float f) {
    unsigned u = __float_as_uint(f);
    return (u & 0x80000000u) ? ~u : (u | 0x80000000u);
}
__device__ __forceinline__ float dec_f(unsigned u) {
    return (u & 0x80000000u) ? __uint_as_float(u ^ 0x80000000u) : __uint_as_float(~u);
}

// ---------------------------------------------------------------------------
// prep: bf16 conversions + zero counts
// ---------------------------------------------------------------------------
__global__ void prep_kernel(const float* __restrict__ z, const float* __restrict__ cb) {
    int i = blockIdx.x * blockDim.x + threadIdx.x;
    int stride = gridDim.x * blockDim.x;
    const int ncb4 = LL * KC * DIM / 4;
    for (int j = i; j < ncb4; j += stride) {
        float4 v = reinterpret_cast<const float4*>(cb)[j];
        uint2 o; o.x = pack_bf2(v.x, v.y); o.y = pack_bf2(v.z, v.w);
        reinterpret_cast<uint2*>(g_cb16)[j] = o;
    }
    const int nz4 = NV * DIM / 4;
    for (int j = i; j < nz4; j += stride) {
        float4 v = reinterpret_cast<const float4*>(z)[j];
        uint2 o; o.x = pack_bf2(v.x, v.y); o.y = pack_bf2(v.z, v.w);
        reinterpret_cast<uint2*>(g_r16)[j] = o;
    }
    for (int j = i; j < LL * KC; j += stride) g_counts[j] = 0;
}

__global__ void enorm_kernel(const float* __restrict__ cb) {
    int gw = (blockIdx.x * blockDim.x + threadIdx.x) >> 5;
    int lane = threadIdx.x & 31;
    if (gw >= LL * KC) return;
    const float4* row = reinterpret_cast<const float4*>(cb) + (size_t)gw * (DIM / 4);
    float s = 0.f;
    #pragma unroll
    for (int c = lane; c < DIM / 4; c += 32) {
        float4 v = row[c];
        s += v.x * v.x + v.y * v.y + v.z * v.z + v.w * v.w;
    }
    #pragma unroll
    for (int o = 16; o > 0; o >>= 1) s += __shfl_xor_sync(0xffffffffu, s, o);
    if (lane == 0) g_enorm[gw] = s;
}

__global__ void reset_kernel() {
    int i = blockIdx.x * blockDim.x + threadIdx.x;
    for (int j = i; j < NV; j += gridDim.x * blockDim.x)
        g_best[j] = 0xFFFFFFFFFFFFFFFFull;
    if (i == 0) g_ncand = 0;
}

// ---------------------------------------------------------------------------
// Fused bf16 HMMA GEMM + running row-min + margin candidate emission.
// CTA: 128 rows, 256 threads (8 warps, 2x4). Warp tile 64x32.
// ---------------------------------------------------------------------------
__global__ __launch_bounds__(256)
void vq_mma_kernel(int l) {
    __shared__ __align__(16) __nv_bfloat16 sA[2][128 * SROW];   // 10 KB each
    __shared__ __align__(16) __nv_bfloat16 sB[2][128 * SROW];
    __shared__ unsigned sMin[128];
    __shared__ float sE[N_TILE];

    const int tid = threadIdx.x;
    const int wid = tid >> 5;
    const int lane = tid & 31;
    const int wm = wid >> 2;            // 0..1  : rows wm*64
    const int wn = wid & 3;             // 0..3  : cols wn*32
    const int block_row = blockIdx.x * 128;
    const __nv_bfloat16* __restrict__ Abase = &g_r16[(size_t)block_row * DIM];
    const __nv_bfloat16* __restrict__ cbl = g_cb16 + (size_t)l * KC * DIM;
    const float* __restrict__ enorm = g_enorm + l * KC;

    // gmem->smem tiling coords (two 16B units per thread per matrix)
    const int r0 = tid >> 2, q0 = tid & 3;
    const int r1 = (tid + 256) >> 2, q1 = tid & 3;   // (tid+256)&3 == tid&3

    if (tid < 128) sMin[tid] = 0xFFFFFFFFu;          // synced by first k-loop barrier

    for (int nt = 0; nt < NT; nt++) {
        const int n0 = nt * N_TILE;
        if (tid < N_TILE) sE[tid] = __ldg(&enorm[n0 + tid]);

        float c[4][4][4];
        #pragma unroll
        for (int ms = 0; ms < 4; ms++)
            #pragma unroll
            for (int ns = 0; ns < 4; ns++)
                #pragma unroll
                for (int e = 0; e < 4; e++) c[ms][ns][e] = 0.f;

        uint4 pa0, pa1, pb0, pb1;
        // prologue: chunk 0
        pa0 = *reinterpret_cast<const uint4*>(&Abase[(size_t)r0 * DIM + q0 * 8]);
        pa1 = *reinterpret_cast<const uint4*>(&Abase[(size_t)r1 * DIM + q1 * 8]);
        pb0 = *reinterpret_cast<const uint4*>(&cbl[(size_t)(n0 + r0) * DIM + q0 * 8]);
        pb1 = *reinterpret_cast<const uint4*>(&cbl[(size_t)(n0 + r1) * DIM + q1 * 8]);
        *reinterpret_cast<uint4*>(&sA[0][r0 * SROW + q0 * 8]) = pa0;
        *reinterpret_cast<uint4*>(&sA[0][r1 * SROW + q1 * 8]) = pa1;
        *reinterpret_cast<uint4*>(&sB[0][r0 * SROW + q0 * 8]) = pb0;
        *reinterpret_cast<uint4*>(&sB[0][r1 * SROW + q1 * 8]) = pb1;
        __syncthreads();

        for (int kc = 0; kc < NKC; kc++) {
            const bool have_next = (kc + 1 < NKC);
            if (have_next) {
                int ko = (kc + 1) * KB;
                pa0 = *reinterpret_cast<const uint4*>(&Abase[(size_t)r0 * DIM + ko + q0 * 8]);
                pa1 = *reinterpret_cast<const uint4*>(&Abase[(size_t)r1 * DIM + ko + q1 * 8]);
                pb0 = *reinterpret_cast<const uint4*>(&cbl[(size_t)(n0 + r0) * DIM + ko + q0 * 8]);
                pb1 = *reinterpret_cast<const uint4*>(&cbl[(size_t)(n0 + r1) * DIM + ko + q1 * 8]);
            }
            // compute current chunk (2 k16 steps)
            const uint32_t aS = smem_u32(sA[kc & 1]);
            const uint32_t bS = smem_u32(sB[kc & 1]);
            #pragma unroll
            for (int ks = 0; ks < 2; ks++) {
                const int koq = ks * 2;
                uint32_t bf0[4], bf1[4];
                #pragma unroll
                for (int ns = 0; ns < 4; ns++) {
                    uint32_t addr = bS + (uint32_t)(wn * 32 + ns * 8 + (lane & 7)) * 80u
                                  + (uint32_t)(koq + ((lane >> 3) & 1)) * 16u;
                    ldsm_x2(bf0[ns], bf1[ns], addr);
                }
                #pragma unroll
                for (int ms = 0; ms < 4; ms++) {
                    uint32_t addr = aS + (uint32_t)(wm * 64 + ms * 16 + (lane & 15)) * 80u
                                  + (uint32_t)(koq + (lane >> 4)) * 16u;
                    uint32_t a0, a1, a2, a3;
                    ldsm_x4(a0, a1, a2, a3, addr);
                    #pragma unroll
                    for (int ns = 0; ns < 4; ns++)
                        mma_bf16(c[ms][ns], a0, a1, a2, a3, bf0[ns], bf1[ns]);
                }
            }
            __syncthreads();
            if (have_next) {
                __nv_bfloat16* dA = sA[(kc + 1) & 1];
                __nv_bfloat16* dB = sB[(kc + 1) & 1];
                *reinterpret_cast<uint4*>(&dA[r0 * SROW + q0 * 8]) = pa0;
                *reinterpret_cast<uint4*>(&dA[r1 * SROW + q1 * 8]) = pa1;
                *reinterpret_cast<uint4*>(&dB[r0 * SROW + q0 * 8]) = pb0;
                *reinterpret_cast<uint4*>(&dB[r1 * SROW + q1 * 8]) = pb1;
                __syncthreads();
            }
        }

        // ---- epilogue: update running row-min, then emit margin candidates
        #pragma unroll
        for (int ms = 0; ms < 4; ms++) {
            float mn0 = FLT_MAX, mn1 = FLT_MAX;
            #pragma unroll
            for (int ns = 0; ns < 4; ns++) {
                int nl = wn * 32 + ns * 8 + (lane & 3) * 2;
                float e0 = sE[nl], e1 = sE[nl + 1];
                mn0 = fminf(mn0, fminf(fmaf(-2.f, c[ms][ns][0], e0),
                                       fmaf(-2.f, c[ms][ns][1], e1)));
                mn1 = fminf(mn1, fminf(fmaf(-2.f, c[ms][ns][2], e0),
                                       fmaf(-2.f, c[ms][ns][3], e1)));
            }
            int m0 = wm * 64 + ms * 16 + (lane >> 2);
            atomicMin(&sMin[m0], enc_f(mn0));
            atomicMin(&sMin[m0 + 8], enc_f(mn1));
        }
        __syncthreads();
        #pragma unroll
        for (int ms = 0; ms < 4; ms++) {
            int m0 = wm * 64 + ms * 16 + (lane >> 2);
            float thr0 = dec_f(sMin[m0]) + MARGIN;
            float thr1 = dec_f(sMin[m0 + 8]) + MARGIN;
            #pragma unroll
            for (int ns = 0; ns < 4; ns++) {
                int nl = wn * 32 + ns * 8 + (lane & 3) * 2;
                float e0 = sE[nl], e1 = sE[nl + 1];
                float v[4] = { fmaf(-2.f, c[ms][ns][0], e0), fmaf(-2.f, c[ms][ns][1], e1),
                               fmaf(-2.f, c[ms][ns][2], e0), fmaf(-2.f, c[ms][ns][3], e1) };
                #pragma unroll
                for (int e = 0; e < 4; e++) {
                    bool emit = v[e] < ((e < 2) ? thr0 : thr1);
                    unsigned mask = __ballot_sync(0xffffffffu, emit);
                    if (mask) {
                        unsigned base = 0;
                        if (lane == 0) base = atomicAdd(&g_ncand, (unsigned)__popc(mask));
                        base = __shfl_sync(0xffffffffu, base, 0);
                        if (emit) {
                            unsigned pos = base + __popc(mask & ((1u << lane) - 1u));
                            unsigned row = (unsigned)(block_row + m0 + ((e < 2) ? 0 : 8));
                            unsigned col = (unsigned)(n0 + nl + (e & 1));
                            if (pos < CAP) g_cand[pos] = (row << 12) | col;
                        }
                    }
                }
            }
        }
        __syncthreads();
    }
}

// ---------------------------------------------------------------------------
// Exact rescore (fp64 accumulation), atomicMin on packed (key, idx)
// ---------------------------------------------------------------------------
__global__ void rescore_kernel(const float* __restrict__ cb, int l) {
    const int lane = threadIdx.x & 31;
    const int wg = (blockIdx.x * blockDim.x + threadIdx.x) >> 5;
    const int nwarp = (gridDim.x * blockDim.x) >> 5;
    unsigned n = g_ncand; if (n > CAP) n = CAP;
    const float* enorm = g_enorm + l * KC;
    for (unsigned i = wg; i < n; i += nwarp) {
        unsigned cnd = g_cand[i];
        unsigned row = cnd >> 12, col = cnd & 4095u;
        const float4* r4 = reinterpret_cast<const float4*>(&g_res[(size_t)row * DIM]);
        const float4* e4 = reinterpret_cast<const float4*>(&cb[(size_t)col * DIM]);
        double acc = 0.0;
        #pragma unroll
        for (int q = 0; q < 4; q++) {
            float4 a = r4[q * 32 + lane];
            float4 b = e4[q * 32 + lane];
            acc += (double)a.x * b.x + (double)a.y * b.y
                 + (double)a.z * b.z + (double)a.w * b.w;
        }
        #pragma unroll
        for (int o = 16; o > 0; o >>= 1)
            acc += __shfl_xor_sync(0xffffffffu, acc, o);
        if (lane == 0) {
            float val = (float)((double)enorm[col] - 2.0 * acc);
            unsigned long long pk = ((unsigned long long)enc_f(val) << 32) | col;
            atomicMin(&g_best[row], pk);
        }
    }
}

// ---------------------------------------------------------------------------
// Gather + STE + residual update (fp32 + bf16 mirror) + commit + histogram
// ---------------------------------------------------------------------------
__global__ void update_kernel(const float* __restrict__ E,
                              float* __restrict__ qsum,
                              float* __restrict__ idx_out, int l) {
    __shared__ float red[512];
    int t = threadIdx.x;
    int row = blockIdx.x * UPD_ROWS + (t >> 7);
    int lane = t & 127;
    int idx = (int)(g_best[row] & 0xFFFFFFFFull) & (KC - 1);

    const float4 q = reinterpret_cast<const float4*>(E)[(size_t)idx * (DIM / 4) + lane];
    float4* rp = reinterpret_cast<float4*>(g_res) + (size_t)row * (DIM / 4) + lane;
    float4 r = *rp;

    float4 qst = make_float4(r.x + (q.x - r.x), r.y + (q.y - r.y),
                             r.z + (q.z - r.z), r.w + (q.w - r.w));
    float4* qp = reinterpret_cast<float4*>(qsum) + (size_t)row * (DIM / 4) + lane;
    if (l == 0) {
        *qp = qst;
    } else {
        float4 p = *qp;
        p.x += qst.x; p.y += qst.y; p.z += qst.z; p.w += qst.w;
        *qp = p;
    }

    float4 d = make_float4(r.x - q.x, r.y - q.y, r.z - q.z, r.w - q.w);
    *rp = d;
    uint2 d16; d16.x = pack_bf2(d.x, d.y); d16.y = pack_bf2(d.z, d.w);
    reinterpret_cast<uint2*>(g_r16)[(size_t)row * (DIM / 4) + lane] = d16;
    float s = d.x * d.x + d.y * d.y + d.z * d.z + d.w * d.w;

    red[t] = s; __syncthreads();
    #pragma unroll
    for (int o = 256; o > 0; o >>= 1) { if (t < o) red[t] += red[t + o]; __syncthreads(); }
    if (t == 0) g_commit[l * UPD_BLOCKS + blockIdx.x] = red[0];

    if (lane == 0) {
        atomicAdd(&g_counts[l * KC + idx], 1);
        idx_out[row * LL] = (float)idx;
    }
}

__global__ void final_kernel(float* __restrict__ out) {
    __shared__ float red[256];
    __shared__ float perp_acc;
    int t = threadIdx.x;

    float s = 0.f;
    for (int i = t; i < LL * UPD_BLOCKS; i += 256) s += g_commit[i];
    red[t] = s; __syncthreads();
    #pragma unroll
    for (int o = 128; o > 0; o >>= 1) { if (t < o) red[t] += red[t + o]; __syncthreads(); }
    float commit = 0.25f * red[0] / (float)((long long)NV * DIM);
    __syncthreads();

    if (t == 0) perp_acc = 0.f;
    for (int l = 0; l < LL; l++) {
        __syncthreads();
        float p = 0.f;
        for (int i = t; i < KC; i += 256) {
            float ap = (float)g_counts[l * KC + i] / (float)NV;
            p += ap * logf(ap + 1e-10f);
        }
        red[t] = p; __syncthreads();
        #pragma unroll
        for (int o = 128; o > 0; o >>= 1) { if (t < o) red[t] += red[t + o]; __syncthreads(); }
        if (t == 0) perp_acc += expf(-red[0]);
    }
    __syncthreads();
    if (t == 0) {
        out[OUT_COMMIT] = commit;
        out[OUT_PERP]   = perp_acc / (float)LL;
    }
}

// ---------------------------------------------------------------------------
extern "C" void kernel_launch(void* const* d_in, const int* in_sizes, int n_in,
                              void* d_out, int out_size) {
    const float* z  = (const float*)d_in[0];
    const float* cb = (const float*)d_in[1];
    float* out = (float*)d_out;

    float* res_ptr = nullptr;
    cudaGetSymbolAddress((void**)&res_ptr, g_res);
    cudaMemcpyAsync(res_ptr, z, (size_t)NV * DIM * sizeof(float),
                    cudaMemcpyDeviceToDevice);

    prep_kernel<<<1024, 256>>>(z, cb);
    enorm_kernel<<<(LL * KC * 32) / 256, 256>>>(cb);

    for (int l = 0; l < LL; l++) {
        const float* E = cb + (size_t)l * KC * DIM;
        reset_kernel<<<128, 256>>>();
        vq_mma_kernel<<<NV / 128, 256>>>(l);
        rescore_kernel<<<512, 256>>>(E, l);
        update_kernel<<<UPD_BLOCKS, 512>>>(E, out + OUT_QSUM, out + OUT_IDX + l, l);
    }
    final_kernel<<<1, 256>>>(out);
}